// round 10
// baseline (speedup 1.0000x reference)
#include <cuda_runtime.h>
#include <cuda_fp16.h>
#include <cstdint>

#define BATCH    32
#define CIN      192
#define T_FRAMES 8192
#define H        192
#define NPH      1024
#define NOUT     4
#define EPS      1e-5f

#define JT 64
#define NTHR 256

// scales (compile-time, power of 2):
//   xh8 = rn(xh * 2^3)   (|act| <= 15.9 : LN bound 13.86, others far smaller)
//   xl8 = rn(xl * 2^14)  (|xl| <= 2^-11 * 15.9 = 7.76e-3 ~ 127*2^-14)
//   wh8 = rn(wh * 2^10)  (|w| <= 0.124, actual ~0.1 max)
//   wl8 = rn(wl * 2^21)  (|wl| <= 2^-11*0.124 = 6.1e-5 <= 127*2^-21)
//   xl8*wh8 and xh8*wl8 both carry scale 2^-24
#define FOLD_SCALE 5.9604644775390625e-8f   // 2^-24

// ---- smem layout (bytes) ----
#define SM_BUF0  5504
#define OF_A16   0
#define OF_B16   9216
#define OF_A8H   36864
#define OF_A8L   41984
#define OF_B8H   47104
#define OF_B8L   62464
#define BUF_STRIDE 77824
#define SMEM_BYTES (SM_BUF0 + 2 * BUF_STRIDE)   // 161152

// ---- device scratch ----
#define PLANE (BATCH * NPH * H)
__device__ __align__(16) int g_ends[BATCH * NPH];
__device__ __align__(16) __half g_spec_h[PLANE];
__device__ __align__(16) char  g_spec_8h[PLANE], g_spec_8l[PLANE];
__device__ __align__(16) __half g_h0_h[PLANE];
__device__ __align__(16) char  g_h0_8h[PLANE], g_h0_8l[PLANE];
__device__ __align__(16) __half g_a0_h[PLANE];
__device__ __align__(16) char  g_a0_8h[PLANE], g_a0_8l[PLANE];
#define WTOT (21 * 12288)
__device__ __align__(16) __half g_wh[WTOT];
__device__ __align__(16) char  g_w8h[WTOT], g_w8l[WTOT];

// ===================== helpers =====================
__device__ __forceinline__ uint32_t smem_u32(const void* p) {
    uint32_t a;
    asm("{ .reg .u64 t; cvta.to.shared.u64 t, %1; cvt.u32.u64 %0, t; }" : "=r"(a) : "l"(p));
    return a;
}
__device__ __forceinline__ void cp16(uint32_t dst, const void* src, uint32_t nbytes) {
    asm volatile("cp.async.cg.shared.global [%0], [%1], 16, %2;"
                 :: "r"(dst), "l"(src), "r"(nbytes) : "memory");
}
__device__ __forceinline__ void cp_commit() {
    asm volatile("cp.async.commit_group;" ::: "memory");
}
template <int N>
__device__ __forceinline__ void cp_wait() {
    asm volatile("cp.async.wait_group %0;" :: "n"(N) : "memory");
}
__device__ __forceinline__ void ldsm4(uint32_t* r, uint32_t a) {
    asm volatile("ldmatrix.sync.aligned.m8n8.x4.shared.b16 {%0,%1,%2,%3}, [%4];"
        : "=r"(r[0]), "=r"(r[1]), "=r"(r[2]), "=r"(r[3]) : "r"(a));
}
__device__ __forceinline__ void mma_f16(float* d, const uint32_t* a, const uint32_t* bq) {
    asm volatile("mma.sync.aligned.m16n8k16.row.col.f32.f16.f16.f32 "
        "{%0,%1,%2,%3}, {%4,%5,%6,%7}, {%8,%9}, {%0,%1,%2,%3};"
        : "+f"(d[0]), "+f"(d[1]), "+f"(d[2]), "+f"(d[3])
        : "r"(a[0]), "r"(a[1]), "r"(a[2]), "r"(a[3]), "r"(bq[0]), "r"(bq[1]));
}
__device__ __forceinline__ void mma_s8(int* d, const uint32_t* a, const uint32_t* bq) {
    asm volatile("mma.sync.aligned.m16n8k32.row.col.s32.s8.s8.s32 "
        "{%0,%1,%2,%3}, {%4,%5,%6,%7}, {%8,%9}, {%0,%1,%2,%3};"
        : "+r"(d[0]), "+r"(d[1]), "+r"(d[2]), "+r"(d[3])
        : "r"(a[0]), "r"(a[1]), "r"(a[2]), "r"(a[3]), "r"(bq[0]), "r"(bq[1]));
}
__device__ __forceinline__ uint32_t pack_f16(float hi_el, float lo_el) { // lo16 = lo_el
    uint32_t r;
    asm("cvt.rn.f16x2.f32 %0, %1, %2;" : "=r"(r) : "f"(hi_el), "f"(lo_el));
    return r;
}
__device__ __forceinline__ int clampi(int v) {
    return v < -127 ? -127 : (v > 127 ? 127 : v);
}
__device__ __forceinline__ uint16_t pack2s8(int q0, int q1) {
    return (uint16_t)((q0 & 0xFF) | ((q1 & 0xFF) << 8));
}

// ===================== 0) weight prep: fp16 hi + int8 planes, im2col order =====================
__global__ void k_prep_w(const float* __restrict__ prew, const float* __restrict__ c0w,
                         const float* __restrict__ c1w) {
    for (int idx = blockIdx.x * blockDim.x + threadIdx.x; idx < WTOT; idx += gridDim.x * blockDim.x) {
        int chunk = idx / 12288, rem = idx % 12288;
        int oc = rem >> 6, i = rem & 63;
        float v;
        if (chunk < 3) {
            v = prew[oc * CIN + chunk * 64 + i];
        } else if (chunk < 12) {
            int cc = chunk - 3, tau = cc / 3, ic = (cc % 3) * 64 + i;
            v = c0w[(oc * H + ic) * 3 + tau];
        } else {
            int cc = chunk - 12, tau = cc / 3, ic = (cc % 3) * 64 + i;
            v = c1w[(oc * H + ic) * 3 + tau];
        }
        __half wh = __float2half_rn(v);
        g_wh[idx] = wh;
        float whf = __half2float(wh);
        g_w8h[idx] = (char)clampi(__float2int_rn(whf * 1024.f));        // 2^10
        g_w8l[idx] = (char)clampi(__float2int_rn((v - whf) * 2097152.f)); // 2^21
    }
}

// ===================== 1) per-batch inclusive scan =====================
__global__ void k_cumsum(const int* __restrict__ w) {
    __shared__ int s[NPH];
    int b = blockIdx.x, t = threadIdx.x;
    s[t] = w[b * NPH + t];
    __syncthreads();
    for (int off = 1; off < NPH; off <<= 1) {
        int v = (t >= off) ? s[t - off] : 0;
        __syncthreads();
        s[t] += v;
        __syncthreads();
    }
    g_ends[b * NPH + t] = s[t];
}

// ===================== 2) segment mean -> fp16 + int8 planes [b][j][c] =====================
#define SEG_J 8
__global__ void k_segmean(const float* __restrict__ x) {
    __shared__ float fr[CIN][SEG_J * 7 + 1];
    __shared__ int se[SEG_J + 1];
    int b = blockIdx.y, j0 = blockIdx.x * SEG_J, tid = threadIdx.x;
    if (tid <= SEG_J) {
        int j = j0 + tid - 1;
        se[tid] = (j >= 0) ? g_ends[b * NPH + j] : 0;
    }
    __syncthreads();
    int t0 = se[0], L = se[SEG_J] - t0;
    const float* xb = x + (size_t)b * CIN * T_FRAMES + t0;
    for (int idx = tid; idx < CIN * L; idx += blockDim.x) {
        int c = idx / L, tt = idx - c * L;
        fr[c][tt] = xb[c * T_FRAMES + tt];
    }
    __syncthreads();
    for (int idx = tid; idx < CIN * SEG_J; idx += blockDim.x) {
        int c = idx >> 3, jj = idx & 7;
        int s = se[jj] - t0, e = se[jj + 1] - t0;
        float acc = 0.f;
        for (int tt = s; tt < e; ++tt) acc += fr[c][tt];
        float v = (e > s) ? acc / (float)(e - s) : 0.f;
        int o = (b * NPH + j0 + jj) * H + c;
        __half hv = __float2half_rn(v);
        g_spec_h[o] = hv;
        float hvf = __half2float(hv);
        g_spec_8h[o] = (char)clampi(__float2int_rn(hvf * 8.f));            // 2^3
        g_spec_8l[o] = (char)clampi(__float2int_rn((v - hvf) * 16384.f));  // 2^14
    }
}

// ===================== 3) fused GEMM layer: fp16 main + int8 corrections =====================
template <int NCHUNKS, int NTAPS, int MODE>
__global__ void __launch_bounds__(NTHR, 1)
k_fused(const float* __restrict__ bias_g, const float* __restrict__ xmask,
        const float* __restrict__ lng, const float* __restrict__ lnb,
        const float* __restrict__ linw, const float* __restrict__ linb,
        int wofs, float* __restrict__ outp) {
    extern __shared__ char smem[];
    const uint32_t sb = smem_u32(smem);
    const int tid  = threadIdx.x;
    const int lane = tid & 31;
    const int wid  = tid >> 5;
    const int wm   = wid >> 2;   // 0..1 (m 32-slice)
    const int wn   = wid & 3;    // 0..3 (n 48-slice)
    const int b    = blockIdx.y;
    const int j0   = blockIdx.x * JT;

    const uint32_t* inH = (const uint32_t*)(MODE == 0 ? g_spec_h : (MODE == 1 ? g_h0_h : g_a0_h));
    const char* in8H = (MODE == 0 ? g_spec_8h : (MODE == 1 ? g_h0_8h : g_a0_8h));
    const char* in8L = (MODE == 0 ? g_spec_8l : (MODE == 1 ? g_h0_8l : g_a0_8l));
    uint32_t* outH = (uint32_t*)(MODE == 0 ? g_h0_h : g_a0_h);
    char* out8H = (MODE == 0 ? g_h0_8h : g_a0_8h);
    char* out8L = (MODE == 0 ? g_h0_8l : g_a0_8l);
    const char* wh16 = (const char*)g_wh + (size_t)wofs * 2;
    const char* w8h  = g_w8h + wofs;
    const char* w8l  = g_w8l + wofs;

    float* par = (float*)smem;
    for (int i = tid; i < H; i += NTHR) par[i] = bias_g[i];
    if (MODE != 0)
        for (int i = tid; i < H; i += NTHR) { par[192 + i] = lng[i]; par[384 + i] = lnb[i]; }
    if (MODE == 2) {
        for (int i = tid; i < NOUT * H; i += NTHR) par[576 + i] = linw[i];
        if (tid < NOUT) par[1344 + tid] = linb[tid];
    }

    auto stage = [&](int c, int bi) {
        const int tau = (NTAPS == 3) ? c / 3 : 0;
        const int icb = (NTAPS == 3) ? c % 3 : c;
        const uint32_t bufb = sb + SM_BUF0 + bi * BUF_STRIDE;
        // A fp16: 64 rows x 8 x 16B
#pragma unroll
        for (int i = 0; i < 2; i++) {
            int idx = tid + i * NTHR;
            int row = idx >> 3, seg = idx & 7;
            int jr = j0 + row + ((NTAPS == 3) ? tau - 1 : 0);
            uint32_t ok = ((unsigned)jr < NPH) ? 16u : 0u;
            int jrc = (jr < 0) ? 0 : (jr >= NPH ? NPH - 1 : jr);
            const uint32_t* src = inH + (b * NPH + jrc) * 96 + icb * 32 + seg * 4;
            cp16(bufb + OF_A16 + (uint32_t)(row * 144 + seg * 16), src, ok);
        }
        // A int8 planes: 64 rows x 4 x 16B each
        {
            int row = tid >> 2, seg = tid & 3;
            int jr = j0 + row + ((NTAPS == 3) ? tau - 1 : 0);
            uint32_t ok = ((unsigned)jr < NPH) ? 16u : 0u;
            int jrc = (jr < 0) ? 0 : (jr >= NPH ? NPH - 1 : jr);
            size_t srcb = (size_t)(b * NPH + jrc) * 192 + icb * 64 + seg * 16;
            uint32_t d = (uint32_t)(row * 80 + seg * 16);
            cp16(bufb + OF_A8H + d, in8H + srcb, ok);
            cp16(bufb + OF_A8L + d, in8L + srcb, ok);
        }
        // B fp16: 192 rows x 8 x 16B
#pragma unroll
        for (int i = 0; i < 6; i++) {
            int idx = tid + i * NTHR;
            int row = idx >> 3, seg = idx & 7;
            const char* src = wh16 + (size_t)c * 24576 + row * 128 + seg * 16;
            cp16(bufb + OF_B16 + (uint32_t)(row * 144 + seg * 16), src, 16u);
        }
        // B int8 planes: 192 rows x 4 x 16B each
#pragma unroll
        for (int i = 0; i < 3; i++) {
            int idx = tid + i * NTHR;
            int row = idx >> 2, seg = idx & 3;
            size_t srcb = (size_t)c * 12288 + row * 64 + seg * 16;
            uint32_t d = (uint32_t)(row * 80 + seg * 16);
            cp16(bufb + OF_B8H + d, w8h + srcb, 16u);
            cp16(bufb + OF_B8L + d, w8l + srcb, 16u);
        }
        cp_commit();
    };

    float acc[2][6][4];
    int   corr[2][6][4];
#pragma unroll
    for (int mt = 0; mt < 2; mt++)
#pragma unroll
        for (int nt = 0; nt < 6; nt++)
#pragma unroll
            for (int q = 0; q < 4; q++) { acc[mt][nt][q] = 0.f; corr[mt][nt][q] = 0; }

    stage(0, 0);

#pragma unroll 1
    for (int c = 0; c < NCHUNKS; c++) {
        __syncthreads();
        if (c + 1 < NCHUNKS) stage(c + 1, (c + 1) & 1);
        if (c + 1 < NCHUNKS) cp_wait<1>(); else cp_wait<0>();
        __syncthreads();
        const uint32_t bufb = sb + SM_BUF0 + (c & 1) * BUF_STRIDE;

        // ---- fp16 main term ----
#pragma unroll 1
        for (int ks = 0; ks < 4; ks++) {
            uint32_t ah[2][4], bh[6][2];
            {
                int t = lane >> 3, r = lane & 7;
                int rowA = 32 * wm + r + ((t & 1) << 3);
                int colA = (ks << 4) + ((t & 2) << 2);
                uint32_t aoff = (uint32_t)(rowA * 144 + colA * 2);
#pragma unroll
                for (int mt = 0; mt < 2; mt++)
                    ldsm4(ah[mt], bufb + OF_A16 + aoff + mt * (16 * 144));
                int g = lane >> 3, rr = lane & 7;
                int rowBb = 48 * wn + ((g >> 1) << 3) + rr;
                int colB = (ks << 4) + ((g & 1) << 3);
                uint32_t boff0 = (uint32_t)(rowBb * 144 + colB * 2);
#pragma unroll
                for (int p = 0; p < 3; p++) {
                    uint32_t tmp[4];
                    ldsm4(tmp, bufb + OF_B16 + boff0 + p * (16 * 144));
                    bh[2 * p][0] = tmp[0]; bh[2 * p][1] = tmp[1];
                    bh[2 * p + 1][0] = tmp[2]; bh[2 * p + 1][1] = tmp[3];
                }
            }
#pragma unroll
            for (int mt = 0; mt < 2; mt++)
#pragma unroll
                for (int nt = 0; nt < 6; nt++)
                    mma_f16(acc[mt][nt], ah[mt], bh[nt]);
        }

        // ---- int8 correction terms (K=32 per mma, 2 steps) ----
#pragma unroll
        for (int ks2 = 0; ks2 < 2; ks2++) {
            const int g = lane >> 2, tig = lane & 3;
            uint32_t a_lo[2][4], a_hi[2][4];
#pragma unroll
            for (int mt = 0; mt < 2; mt++) {
                uint32_t o = (uint32_t)((32 * wm + 16 * mt + g) * 80 + ks2 * 32 + tig * 4);
                a_lo[mt][0] = *(const uint32_t*)(smem + (bufb - sb) + OF_A8L + o);
                a_lo[mt][1] = *(const uint32_t*)(smem + (bufb - sb) + OF_A8L + o + 640);
                a_lo[mt][2] = *(const uint32_t*)(smem + (bufb - sb) + OF_A8L + o + 16);
                a_lo[mt][3] = *(const uint32_t*)(smem + (bufb - sb) + OF_A8L + o + 656);
                a_hi[mt][0] = *(const uint32_t*)(smem + (bufb - sb) + OF_A8H + o);
                a_hi[mt][1] = *(const uint32_t*)(smem + (bufb - sb) + OF_A8H + o + 640);
                a_hi[mt][2] = *(const uint32_t*)(smem + (bufb - sb) + OF_A8H + o + 16);
                a_hi[mt][3] = *(const uint32_t*)(smem + (bufb - sb) + OF_A8H + o + 656);
            }
            uint32_t bwh[6][2], bwl[6][2];
#pragma unroll
            for (int nt = 0; nt < 6; nt++) {
                uint32_t ob = (uint32_t)((48 * wn + 8 * nt + g) * 80 + ks2 * 32 + tig * 4);
                bwh[nt][0] = *(const uint32_t*)(smem + (bufb - sb) + OF_B8H + ob);
                bwh[nt][1] = *(const uint32_t*)(smem + (bufb - sb) + OF_B8H + ob + 16);
                bwl[nt][0] = *(const uint32_t*)(smem + (bufb - sb) + OF_B8L + ob);
                bwl[nt][1] = *(const uint32_t*)(smem + (bufb - sb) + OF_B8L + ob + 16);
            }
#pragma unroll
            for (int mt = 0; mt < 2; mt++)
#pragma unroll
                for (int nt = 0; nt < 6; nt++) {
                    mma_s8(corr[mt][nt], a_lo[mt], bwh[nt]);   // xl * wh
                    mma_s8(corr[mt][nt], a_hi[mt], bwl[nt]);   // xh * wl
                }
        }
    }
    // fold corrections into main accumulators
#pragma unroll
    for (int mt = 0; mt < 2; mt++)
#pragma unroll
        for (int nt = 0; nt < 6; nt++)
#pragma unroll
            for (int q = 0; q < 4; q++)
                acc[mt][nt][q] += (float)corr[mt][nt][q] * FOLD_SCALE;

    __syncthreads();   // stage smem dead; safe to overlay reductions

    if (MODE == 0) {
#pragma unroll
        for (int mt = 0; mt < 2; mt++)
#pragma unroll
            for (int t = 0; t < 2; t++) {
                int jloc = 32 * wm + 16 * mt + (lane >> 2) + 8 * t;
                int j = j0 + jloc;
                float m = xmask[b * NPH + j];
                uint32_t* oH = outH + (b * NPH + j) * 96;
                uint16_t* o8h = (uint16_t*)(out8H + (size_t)(b * NPH + j) * 192);
                uint16_t* o8l = (uint16_t*)(out8L + (size_t)(b * NPH + j) * 192);
#pragma unroll
                for (int nt = 0; nt < 6; nt++) {
                    int c0 = 48 * wn + 8 * nt + (lane & 3) * 2;
                    float v0 = (acc[mt][nt][2 * t + 0] + par[c0])     * m;
                    float v1 = (acc[mt][nt][2 * t + 1] + par[c0 + 1]) * m;
                    uint32_t ph = pack_f16(v1, v0);
                    float h0f = __half2float(__ushort_as_half((unsigned short)(ph & 0xFFFF)));
                    float h1f = __half2float(__ushort_as_half((unsigned short)(ph >> 16)));
                    oH[c0 >> 1] = ph;
                    o8h[c0 >> 1] = pack2s8(clampi(__float2int_rn(h0f * 8.f)),
                                           clampi(__float2int_rn(h1f * 8.f)));
                    o8l[c0 >> 1] = pack2s8(clampi(__float2int_rn((v0 - h0f) * 16384.f)),
                                           clampi(__float2int_rn((v1 - h1f) * 16384.f)));
                }
            }
        return;
    }

    float* redS1 = (float*)(smem + SM_BUF0);        // [64][4]
    float* redS2 = redS1 + 256;                     // [64][4]
    float* redLin = redS2 + 256;                    // [4][64][4]

#pragma unroll
    for (int mt = 0; mt < 2; mt++)
#pragma unroll
        for (int t = 0; t < 2; t++) {
            int jloc = 32 * wm + 16 * mt + (lane >> 2) + 8 * t;
            float m = xmask[b * NPH + j0 + jloc];
            float s1 = 0.f, s2 = 0.f;
#pragma unroll
            for (int nt = 0; nt < 6; nt++) {
                int c0 = 48 * wn + 8 * nt + (lane & 3) * 2;
#pragma unroll
                for (int q = 0; q < 2; q++) {
                    float v = fmaxf((acc[mt][nt][2 * t + q] + par[c0 + q]) * m, 0.f) * m;
                    s1 += v; s2 += v * v;
                }
            }
            s1 += __shfl_xor_sync(0xffffffffu, s1, 1); s1 += __shfl_xor_sync(0xffffffffu, s1, 2);
            s2 += __shfl_xor_sync(0xffffffffu, s2, 1); s2 += __shfl_xor_sync(0xffffffffu, s2, 2);
            if ((lane & 3) == 0) { redS1[jloc * 4 + wn] = s1; redS2[jloc * 4 + wn] = s2; }
        }
    __syncthreads();

#pragma unroll
    for (int mt = 0; mt < 2; mt++)
#pragma unroll
        for (int t = 0; t < 2; t++) {
            int jloc = 32 * wm + 16 * mt + (lane >> 2) + 8 * t;
            int j = j0 + jloc;
            float m = xmask[b * NPH + j];
            float s1 = redS1[jloc * 4 + 0] + redS1[jloc * 4 + 1] + redS1[jloc * 4 + 2] + redS1[jloc * 4 + 3];
            float s2 = redS2[jloc * 4 + 0] + redS2[jloc * 4 + 1] + redS2[jloc * 4 + 2] + redS2[jloc * 4 + 3];
            float mean = s1 * (1.f / H);
            float rstd = rsqrtf(s2 * (1.f / H) - mean * mean + EPS);
            if (MODE == 1) {
                uint32_t* oH = outH + (b * NPH + j) * 96;
                uint16_t* o8h = (uint16_t*)(out8H + (size_t)(b * NPH + j) * 192);
                uint16_t* o8l = (uint16_t*)(out8L + (size_t)(b * NPH + j) * 192);
#pragma unroll
                for (int nt = 0; nt < 6; nt++) {
                    int c0 = 48 * wn + 8 * nt + (lane & 3) * 2;
                    float v0 = fmaxf((acc[mt][nt][2 * t + 0] + par[c0])     * m, 0.f) * m;
                    float v1 = fmaxf((acc[mt][nt][2 * t + 1] + par[c0 + 1]) * m, 0.f) * m;
                    float y0 = ((v0 - mean) * rstd * par[192 + c0]     + par[384 + c0])     * m * m;
                    float y1 = ((v1 - mean) * rstd * par[192 + c0 + 1] + par[384 + c0 + 1]) * m * m;
                    uint32_t ph = pack_f16(y1, y0);
                    float h0f = __half2float(__ushort_as_half((unsigned short)(ph & 0xFFFF)));
                    float h1f = __half2float(__ushort_as_half((unsigned short)(ph >> 16)));
                    oH[c0 >> 1] = ph;
                    o8h[c0 >> 1] = pack2s8(clampi(__float2int_rn(h0f * 8.f)),
                                           clampi(__float2int_rn(h1f * 8.f)));
                    o8l[c0 >> 1] = pack2s8(clampi(__float2int_rn((y0 - h0f) * 16384.f)),
                                           clampi(__float2int_rn((y1 - h1f) * 16384.f)));
                }
            } else {
                float p0 = 0.f, p1 = 0.f, p2 = 0.f, p3 = 0.f;
#pragma unroll
                for (int nt = 0; nt < 6; nt++) {
                    int c0 = 48 * wn + 8 * nt + (lane & 3) * 2;
#pragma unroll
                    for (int q = 0; q < 2; q++) {
                        int cc = c0 + q;
                        float v = fmaxf((acc[mt][nt][2 * t + q] + par[cc]) * m, 0.f) * m;
                        float y = ((v - mean) * rstd * par[192 + cc] + par[384 + cc]) * m;
                        p0 += y * par[576 + 0 * H + cc];
                        p1 += y * par[576 + 1 * H + cc];
                        p2 += y * par[576 + 2 * H + cc];
                        p3 += y * par[576 + 3 * H + cc];
                    }
                }
                p0 += __shfl_xor_sync(0xffffffffu, p0, 1); p0 += __shfl_xor_sync(0xffffffffu, p0, 2);
                p1 += __shfl_xor_sync(0xffffffffu, p1, 1); p1 += __shfl_xor_sync(0xffffffffu, p1, 2);
                p2 += __shfl_xor_sync(0xffffffffu, p2, 1); p2 += __shfl_xor_sync(0xffffffffu, p2, 2);
                p3 += __shfl_xor_sync(0xffffffffu, p3, 1); p3 += __shfl_xor_sync(0xffffffffu, p3, 2);
                if ((lane & 3) == 0) {
                    redLin[(0 * 64 + jloc) * 4 + wn] = p0;
                    redLin[(1 * 64 + jloc) * 4 + wn] = p1;
                    redLin[(2 * 64 + jloc) * 4 + wn] = p2;
                    redLin[(3 * 64 + jloc) * 4 + wn] = p3;
                }
            }
        }

    if (MODE == 2) {
        __syncthreads();
        {
            int o = tid >> 6, jl = tid & 63;
            float s = redLin[(o * 64 + jl) * 4 + 0] + redLin[(o * 64 + jl) * 4 + 1]
                    + redLin[(o * 64 + jl) * 4 + 2] + redLin[(o * 64 + jl) * 4 + 3];
            s += par[1344 + o];
            s *= xmask[b * NPH + j0 + jl];
            outp[(b * NOUT + o) * NPH + j0 + jl] = s;
        }
    }
}

// ===================== launch =====================
extern "C" void kernel_launch(void* const* d_in, const int* in_sizes, int n_in,
                              void* d_out, int out_size) {
    (void)in_sizes; (void)n_in; (void)out_size;
    const float* x    = (const float*)d_in[0];
    const float* xm   = (const float*)d_in[1];
    const int*   w    = (const int*)d_in[2];
    const float* prew = (const float*)d_in[3];
    const float* preb = (const float*)d_in[4];
    const float* c0w  = (const float*)d_in[5];
    const float* c0b  = (const float*)d_in[6];
    const float* g0   = (const float*)d_in[7];
    const float* b0   = (const float*)d_in[8];
    const float* c1w  = (const float*)d_in[9];
    const float* c1b  = (const float*)d_in[10];
    const float* g1   = (const float*)d_in[11];
    const float* b1   = (const float*)d_in[12];
    const float* lw   = (const float*)d_in[13];
    const float* lb   = (const float*)d_in[14];
    float* out = (float*)d_out;

    cudaFuncSetAttribute((const void*)k_fused<3, 1, 0>, cudaFuncAttributeMaxDynamicSharedMemorySize, SMEM_BYTES);
    cudaFuncSetAttribute((const void*)k_fused<9, 3, 1>, cudaFuncAttributeMaxDynamicSharedMemorySize, SMEM_BYTES);
    cudaFuncSetAttribute((const void*)k_fused<9, 3, 2>, cudaFuncAttributeMaxDynamicSharedMemorySize, SMEM_BYTES);

    k_prep_w<<<252, 256>>>(prew, c0w, c1w);
    k_cumsum<<<BATCH, NPH>>>(w);
    k_segmean<<<dim3(NPH / SEG_J, BATCH), 256>>>(x);

    dim3 cg(NPH / JT, BATCH);
    k_fused<3, 1, 0><<<cg, NTHR, SMEM_BYTES>>>(preb, xm, nullptr, nullptr, nullptr, nullptr, 0, nullptr);
    k_fused<9, 3, 1><<<cg, NTHR, SMEM_BYTES>>>(c0b, xm, g0, b0, nullptr, nullptr, 3 * 12288, nullptr);
    k_fused<9, 3, 2><<<cg, NTHR, SMEM_BYTES>>>(c1b, xm, g1, b1, lw, lb, 12 * 12288, out);
}

// round 14
// speedup vs baseline: 2.3782x; 2.3782x over previous
#include <cuda_runtime.h>
#include <cuda_fp16.h>
#include <cstdint>

#define BATCH    32
#define CIN      192
#define T_FRAMES 8192
#define H        192
#define NPH      1024
#define NOUT     4
#define EPS      1e-5f

#define JT 128
#define NTHR 256

// ---- smem layout (bytes) ----
#define SM_BUF0   5504
#define OF_AH 0
#define OF_BH 18432
#define OF_BL 46080
#define BUF_STRIDE 73728
#define SMEM_BYTES (SM_BUF0 + 2 * BUF_STRIDE)   // 152960

// ---- device scratch ----
#define PLANE (BATCH * NPH * H)
__device__ __align__(16) int g_ends[BATCH * NPH];
__device__ __align__(16) __half g_spec_h[PLANE];
__device__ __align__(16) __half g_h0_h[PLANE];
__device__ __align__(16) __half g_a0_h[PLANE];
#define WTOT (21 * 12288)
__device__ __align__(16) __half g_w_h[WTOT], g_w_l[WTOT];

// ===================== helpers =====================
__device__ __forceinline__ uint32_t smem_u32(const void* p) {
    uint32_t a;
    asm("{ .reg .u64 t; cvta.to.shared.u64 t, %1; cvt.u32.u64 %0, t; }" : "=r"(a) : "l"(p));
    return a;
}
__device__ __forceinline__ void cp16(uint32_t dst, const void* src, uint32_t nbytes) {
    asm volatile("cp.async.cg.shared.global [%0], [%1], 16, %2;"
                 :: "r"(dst), "l"(src), "r"(nbytes) : "memory");
}
__device__ __forceinline__ void cp_commit() {
    asm volatile("cp.async.commit_group;" ::: "memory");
}
template <int N>
__device__ __forceinline__ void cp_wait() {
    asm volatile("cp.async.wait_group %0;" :: "n"(N) : "memory");
}
__device__ __forceinline__ void ldsm4(uint32_t* r, uint32_t a) {
    asm volatile("ldmatrix.sync.aligned.m8n8.x4.shared.b16 {%0,%1,%2,%3}, [%4];"
        : "=r"(r[0]), "=r"(r[1]), "=r"(r[2]), "=r"(r[3]) : "r"(a));
}
__device__ __forceinline__ void mma_f16(float* d, const uint32_t* a, const uint32_t* bq) {
    asm volatile("mma.sync.aligned.m16n8k16.row.col.f32.f16.f16.f32 "
        "{%0,%1,%2,%3}, {%4,%5,%6,%7}, {%8,%9}, {%0,%1,%2,%3};"
        : "+f"(d[0]), "+f"(d[1]), "+f"(d[2]), "+f"(d[3])
        : "r"(a[0]), "r"(a[1]), "r"(a[2]), "r"(a[3]), "r"(bq[0]), "r"(bq[1]));
}
__device__ __forceinline__ uint32_t pack_f16(float hi_el, float lo_el) { // lo16 = lo_el
    uint32_t r;
    asm("cvt.rn.f16x2.f32 %0, %1, %2;" : "=r"(r) : "f"(hi_el), "f"(lo_el));
    return r;
}

// ===================== 0) weight prep: fp16 hi/lo split + im2col chunk reorder =====================
__global__ void k_prep_w(const float* __restrict__ prew, const float* __restrict__ c0w,
                         const float* __restrict__ c1w) {
    for (int idx = blockIdx.x * blockDim.x + threadIdx.x; idx < WTOT; idx += gridDim.x * blockDim.x) {
        int chunk = idx / 12288, rem = idx % 12288;
        int oc = rem >> 6, i = rem & 63;
        float v;
        if (chunk < 3) {
            v = prew[oc * CIN + chunk * 64 + i];
        } else if (chunk < 12) {
            int cc = chunk - 3, tau = cc / 3, ic = (cc % 3) * 64 + i;
            v = c0w[(oc * H + ic) * 3 + tau];
        } else {
            int cc = chunk - 12, tau = cc / 3, ic = (cc % 3) * 64 + i;
            v = c1w[(oc * H + ic) * 3 + tau];
        }
        __half hb = __float2half_rn(v);
        g_w_h[idx] = hb;
        g_w_l[idx] = __float2half_rn(v - __half2float(hb));
    }
}

// ===================== 1) per-batch inclusive scan =====================
__global__ void k_cumsum(const int* __restrict__ w) {
    __shared__ int s[NPH];
    int b = blockIdx.x, t = threadIdx.x;
    s[t] = w[b * NPH + t];
    __syncthreads();
    for (int off = 1; off < NPH; off <<= 1) {
        int v = (t >= off) ? s[t - off] : 0;
        __syncthreads();
        s[t] += v;
        __syncthreads();
    }
    g_ends[b * NPH + t] = s[t];
}

// ===================== 2) segment mean -> fp16 plane [b][j][c] =====================
#define SEG_J 8
__global__ void k_segmean(const float* __restrict__ x) {
    __shared__ float fr[CIN][SEG_J * 7 + 1];
    __shared__ int se[SEG_J + 1];
    int b = blockIdx.y, j0 = blockIdx.x * SEG_J, tid = threadIdx.x;
    if (tid <= SEG_J) {
        int j = j0 + tid - 1;
        se[tid] = (j >= 0) ? g_ends[b * NPH + j] : 0;
    }
    __syncthreads();
    int t0 = se[0], L = se[SEG_J] - t0;
    const float* xb = x + (size_t)b * CIN * T_FRAMES + t0;
    for (int idx = tid; idx < CIN * L; idx += blockDim.x) {
        int c = idx / L, tt = idx - c * L;
        fr[c][tt] = xb[c * T_FRAMES + tt];
    }
    __syncthreads();
    for (int idx = tid; idx < CIN * SEG_J; idx += blockDim.x) {
        int c = idx >> 3, jj = idx & 7;
        int s = se[jj] - t0, e = se[jj + 1] - t0;
        float acc = 0.f;
        for (int tt = s; tt < e; ++tt) acc += fr[c][tt];
        float v = (e > s) ? acc / (float)(e - s) : 0.f;
        g_spec_h[(b * NPH + j0 + jj) * H + c] = __float2half_rn(v);
    }
}

// ===================== 3) fused HMMA GEMM layer (fp16 2-term) =====================
// MODE 0: pre (K=192): (D+bias)*m -> h0
// MODE 1: conv0 (K=576): relu((D+b)*m)*m -> LN -> *m*m -> a0
// MODE 2: conv1: ... -> LN -> *m -> linear(4) + lb -> *m -> out
template <int NCHUNKS, int NTAPS, int MODE>
__global__ void __launch_bounds__(NTHR, 1)
k_fused(const float* __restrict__ bias_g, const float* __restrict__ xmask,
        const float* __restrict__ lng, const float* __restrict__ lnb,
        const float* __restrict__ linw, const float* __restrict__ linb,
        int wofs, float* __restrict__ outp) {
    extern __shared__ char smem[];
    const uint32_t sb = smem_u32(smem);
    const int tid  = threadIdx.x;
    const int lane = tid & 31;
    const int wid  = tid >> 5;
    const int wm   = wid >> 2;   // 0..1 (m 64-slice)
    const int wn   = wid & 3;    // 0..3 (n 48-slice)
    const int b    = blockIdx.y;
    const int j0   = blockIdx.x * JT;

    const uint32_t* inH = (const uint32_t*)(MODE == 0 ? g_spec_h : (MODE == 1 ? g_h0_h : g_a0_h));
    uint32_t* outH = (uint32_t*)(MODE == 0 ? g_h0_h : g_a0_h);
    const uint32_t* wH = ((const uint32_t*)g_w_h) + (wofs >> 1);
    const uint32_t* wL = ((const uint32_t*)g_w_l) + (wofs >> 1);

    float* par = (float*)smem;
    for (int i = tid; i < H; i += NTHR) par[i] = bias_g[i];
    if (MODE != 0)
        for (int i = tid; i < H; i += NTHR) { par[192 + i] = lng[i]; par[384 + i] = lnb[i]; }
    if (MODE == 2) {
        for (int i = tid; i < NOUT * H; i += NTHR) par[576 + i] = linw[i];
        if (tid < NOUT) par[1344 + tid] = linb[tid];
    }

    auto stage = [&](int c, int bi) {
        const int tau = (NTAPS == 3) ? c / 3 : 0;
        const int icb = (NTAPS == 3) ? c % 3 : c;
        const uint32_t bufb = sb + SM_BUF0 + bi * BUF_STRIDE;
        // A: 128 rows x 8 x 16B (single fp16 plane)
#pragma unroll
        for (int i = 0; i < 4; i++) {
            int idx = tid + i * NTHR;
            int row = idx >> 3, seg = idx & 7;
            int jr = j0 + row + ((NTAPS == 3) ? tau - 1 : 0);
            uint32_t ok = ((unsigned)jr < NPH) ? 16u : 0u;
            int jrc = (jr < 0) ? 0 : (jr >= NPH ? NPH - 1 : jr);
            int s = (b * NPH + jrc) * 96 + icb * 32 + seg * 4;
            cp16(bufb + OF_AH + (uint32_t)(row * 144 + seg * 16), inH + s, ok);
        }
        // B: 192 rows x 8 x 16B per plane (hi + lo)
#pragma unroll
        for (int i = 0; i < 6; i++) {
            int idx = tid + i * NTHR;
            int row = idx >> 3, seg = idx & 7;
            int s = c * 6144 + idx * 4;
            uint32_t d = (uint32_t)(row * 144 + seg * 16);
            cp16(bufb + OF_BH + d, wH + s, 16u);
            cp16(bufb + OF_BL + d, wL + s, 16u);
        }
        cp_commit();
    };

    float acc[4][6][4];
#pragma unroll
    for (int mt = 0; mt < 4; mt++)
#pragma unroll
        for (int nt = 0; nt < 6; nt++)
#pragma unroll
            for (int q = 0; q < 4; q++) acc[mt][nt][q] = 0.f;

    stage(0, 0);

#pragma unroll 1
    for (int c = 0; c < NCHUNKS; c++) {
        __syncthreads();                       // buffer (c+1)&1 free (mma of c-1 done)
        if (c + 1 < NCHUNKS) stage(c + 1, (c + 1) & 1);
        if (c + 1 < NCHUNKS) cp_wait<1>(); else cp_wait<0>();
        __syncthreads();                       // chunk c visible to all warps
        const uint32_t bufb = sb + SM_BUF0 + (c & 1) * BUF_STRIDE;

#pragma unroll 1
        for (int ks = 0; ks < 4; ks++) {
            uint32_t ah[4][4], bh[6][2], bl[6][2];
            {
                int t = lane >> 3, r = lane & 7;
                int rowA = 64 * wm + r + ((t & 1) << 3);
                int colA = (ks << 4) + ((t & 2) << 2);
                uint32_t aoff = (uint32_t)(rowA * 144 + colA * 2);
#pragma unroll
                for (int mt = 0; mt < 4; mt++)
                    ldsm4(ah[mt], bufb + OF_AH + aoff + mt * (16 * 144));
                int g = lane >> 3, rr = lane & 7;
                int rowBb = 48 * wn + ((g >> 1) << 3) + rr;
                int colB = (ks << 4) + ((g & 1) << 3);
                uint32_t boff0 = (uint32_t)(rowBb * 144 + colB * 2);
#pragma unroll
                for (int p = 0; p < 3; p++) {
                    uint32_t tmp[4];
                    ldsm4(tmp, bufb + OF_BH + boff0 + p * (16 * 144));
                    bh[2 * p][0] = tmp[0]; bh[2 * p][1] = tmp[1];
                    bh[2 * p + 1][0] = tmp[2]; bh[2 * p + 1][1] = tmp[3];
                    ldsm4(tmp, bufb + OF_BL + boff0 + p * (16 * 144));
                    bl[2 * p][0] = tmp[0]; bl[2 * p][1] = tmp[1];
                    bl[2 * p + 1][0] = tmp[2]; bl[2 * p + 1][1] = tmp[3];
                }
            }
#pragma unroll
            for (int mt = 0; mt < 4; mt++)
#pragma unroll
                for (int nt = 0; nt < 6; nt++) {
                    mma_f16(acc[mt][nt], ah[mt], bh[nt]);
                    mma_f16(acc[mt][nt], ah[mt], bl[nt]);
                }
        }
    }
    __syncthreads();   // stage smem dead; safe to overlay reductions

    if (MODE == 0) {
#pragma unroll
        for (int mt = 0; mt < 4; mt++)
#pragma unroll
            for (int t = 0; t < 2; t++) {
                int jloc = 64 * wm + 16 * mt + (lane >> 2) + 8 * t;
                int j = j0 + jloc;
                float m = xmask[b * NPH + j];
                uint32_t* oH = outH + (b * NPH + j) * 96;
#pragma unroll
                for (int nt = 0; nt < 6; nt++) {
                    int c0 = 48 * wn + 8 * nt + (lane & 3) * 2;
                    float v0 = (acc[mt][nt][2 * t + 0] + par[c0])     * m;
                    float v1 = (acc[mt][nt][2 * t + 1] + par[c0 + 1]) * m;
                    oH[c0 >> 1] = pack_f16(v1, v0);
                }
            }
        return;
    }

    float* redS1 = (float*)(smem + SM_BUF0);        // [128][4]
    float* redS2 = redS1 + 512;                     // [128][4]
    float* redLin = redS2 + 512;                    // [4][128][4]

#pragma unroll
    for (int mt = 0; mt < 4; mt++)
#pragma unroll
        for (int t = 0; t < 2; t++) {
            int jloc = 64 * wm + 16 * mt + (lane >> 2) + 8 * t;
            float m = xmask[b * NPH + j0 + jloc];
            float s1 = 0.f, s2 = 0.f;
#pragma unroll
            for (int nt = 0; nt < 6; nt++) {
                int c0 = 48 * wn + 8 * nt + (lane & 3) * 2;
#pragma unroll
                for (int q = 0; q < 2; q++) {
                    float v = fmaxf((acc[mt][nt][2 * t + q] + par[c0 + q]) * m, 0.f) * m;
                    s1 += v; s2 += v * v;
                }
            }
            s1 += __shfl_xor_sync(0xffffffffu, s1, 1); s1 += __shfl_xor_sync(0xffffffffu, s1, 2);
            s2 += __shfl_xor_sync(0xffffffffu, s2, 1); s2 += __shfl_xor_sync(0xffffffffu, s2, 2);
            if ((lane & 3) == 0) { redS1[jloc * 4 + wn] = s1; redS2[jloc * 4 + wn] = s2; }
        }
    __syncthreads();

#pragma unroll
    for (int mt = 0; mt < 4; mt++)
#pragma unroll
        for (int t = 0; t < 2; t++) {
            int jloc = 64 * wm + 16 * mt + (lane >> 2) + 8 * t;
            int j = j0 + jloc;
            float m = xmask[b * NPH + j];
            float s1 = redS1[jloc * 4 + 0] + redS1[jloc * 4 + 1] + redS1[jloc * 4 + 2] + redS1[jloc * 4 + 3];
            float s2 = redS2[jloc * 4 + 0] + redS2[jloc * 4 + 1] + redS2[jloc * 4 + 2] + redS2[jloc * 4 + 3];
            float mean = s1 * (1.f / H);
            float rstd = rsqrtf(s2 * (1.f / H) - mean * mean + EPS);
            if (MODE == 1) {
                uint32_t* oH = outH + (b * NPH + j) * 96;
#pragma unroll
                for (int nt = 0; nt < 6; nt++) {
                    int c0 = 48 * wn + 8 * nt + (lane & 3) * 2;
                    float v0 = fmaxf((acc[mt][nt][2 * t + 0] + par[c0])     * m, 0.f) * m;
                    float v1 = fmaxf((acc[mt][nt][2 * t + 1] + par[c0 + 1]) * m, 0.f) * m;
                    float y0 = ((v0 - mean) * rstd * par[192 + c0]     + par[384 + c0])     * m * m;
                    float y1 = ((v1 - mean) * rstd * par[192 + c0 + 1] + par[384 + c0 + 1]) * m * m;
                    oH[c0 >> 1] = pack_f16(y1, y0);
                }
            } else {
                float p0 = 0.f, p1 = 0.f, p2 = 0.f, p3 = 0.f;
#pragma unroll
                for (int nt = 0; nt < 6; nt++) {
                    int c0 = 48 * wn + 8 * nt + (lane & 3) * 2;
#pragma unroll
                    for (int q = 0; q < 2; q++) {
                        int cc = c0 + q;
                        float v = fmaxf((acc[mt][nt][2 * t + q] + par[cc]) * m, 0.f) * m;
                        float y = ((v - mean) * rstd * par[192 + cc] + par[384 + cc]) * m;
                        p0 += y * par[576 + 0 * H + cc];
                        p1 += y * par[576 + 1 * H + cc];
                        p2 += y * par[576 + 2 * H + cc];
                        p3 += y * par[576 + 3 * H + cc];
                    }
                }
                p0 += __shfl_xor_sync(0xffffffffu, p0, 1); p0 += __shfl_xor_sync(0xffffffffu, p0, 2);
                p1 += __shfl_xor_sync(0xffffffffu, p1, 1); p1 += __shfl_xor_sync(0xffffffffu, p1, 2);
                p2 += __shfl_xor_sync(0xffffffffu, p2, 1); p2 += __shfl_xor_sync(0xffffffffu, p2, 2);
                p3 += __shfl_xor_sync(0xffffffffu, p3, 1); p3 += __shfl_xor_sync(0xffffffffu, p3, 2);
                if ((lane & 3) == 0) {
                    redLin[(0 * 128 + jloc) * 4 + wn] = p0;
                    redLin[(1 * 128 + jloc) * 4 + wn] = p1;
                    redLin[(2 * 128 + jloc) * 4 + wn] = p2;
                    redLin[(3 * 128 + jloc) * 4 + wn] = p3;
                }
            }
        }

    if (MODE == 2) {
        __syncthreads();
        for (int oj = tid; oj < 512; oj += NTHR) {
            int o = oj >> 7, jl = oj & 127;
            float s = redLin[(o * 128 + jl) * 4 + 0] + redLin[(o * 128 + jl) * 4 + 1]
                    + redLin[(o * 128 + jl) * 4 + 2] + redLin[(o * 128 + jl) * 4 + 3];
            s += par[1344 + o];
            s *= xmask[b * NPH + j0 + jl];
            outp[(b * NOUT + o) * NPH + j0 + jl] = s;
        }
    }
}

// ===================== launch =====================
extern "C" void kernel_launch(void* const* d_in, const int* in_sizes, int n_in,
                              void* d_out, int out_size) {
    (void)in_sizes; (void)n_in; (void)out_size;
    const float* x    = (const float*)d_in[0];
    const float* xm   = (const float*)d_in[1];
    const int*   w    = (const int*)d_in[2];
    const float* prew = (const float*)d_in[3];
    const float* preb = (const float*)d_in[4];
    const float* c0w  = (const float*)d_in[5];
    const float* c0b  = (const float*)d_in[6];
    const float* g0   = (const float*)d_in[7];
    const float* b0   = (const float*)d_in[8];
    const float* c1w  = (const float*)d_in[9];
    const float* c1b  = (const float*)d_in[10];
    const float* g1   = (const float*)d_in[11];
    const float* b1   = (const float*)d_in[12];
    const float* lw   = (const float*)d_in[13];
    const float* lb   = (const float*)d_in[14];
    float* out = (float*)d_out;

    cudaFuncSetAttribute((const void*)k_fused<3, 1, 0>, cudaFuncAttributeMaxDynamicSharedMemorySize, SMEM_BYTES);
    cudaFuncSetAttribute((const void*)k_fused<9, 3, 1>, cudaFuncAttributeMaxDynamicSharedMemorySize, SMEM_BYTES);
    cudaFuncSetAttribute((const void*)k_fused<9, 3, 2>, cudaFuncAttributeMaxDynamicSharedMemorySize, SMEM_BYTES);

    k_prep_w<<<252, 256>>>(prew, c0w, c1w);
    k_cumsum<<<BATCH, NPH>>>(w);
    k_segmean<<<dim3(NPH / SEG_J, BATCH), 256>>>(x);

    dim3 cg(NPH / JT, BATCH);
    k_fused<3, 1, 0><<<cg, NTHR, SMEM_BYTES>>>(preb, xm, nullptr, nullptr, nullptr, nullptr, 0, nullptr);
    k_fused<9, 3, 1><<<cg, NTHR, SMEM_BYTES>>>(c0b, xm, g0, b0, nullptr, nullptr, 3 * 12288, nullptr);
    k_fused<9, 3, 2><<<cg, NTHR, SMEM_BYTES>>>(c1b, xm, g1, b1, lw, lb, 12 * 12288, out);
}

// round 15
// speedup vs baseline: 2.9039x; 1.2211x over previous
#include <cuda_runtime.h>
#include <cuda_fp16.h>
#include <cstdint>

#define BATCH    32
#define CIN      192
#define T_FRAMES 8192
#define H        192
#define NPH      1024
#define NOUT     4
#define EPS      1e-5f

#define JT 128
#define NTHR 256

// ---- smem layout (bytes) ----
#define SM_BUF0   5504
#define OF_AH 0
#define OF_BH 18432
#define OF_BL 46080
#define BUF_STRIDE 73728
#define SMEM_BYTES (SM_BUF0 + 2 * BUF_STRIDE)   // 152960

// ---- device scratch ----
#define PLANE (BATCH * NPH * H)
__device__ __align__(16) int g_ends[BATCH * NPH];
__device__ __align__(16) __half g_spec_h[PLANE];
__device__ __align__(16) __half g_h0_h[PLANE];
__device__ __align__(16) __half g_a0_h[PLANE];
#define WTOT (21 * 12288)
__device__ __align__(16) __half g_w_h[WTOT], g_w_l[WTOT];

// ===================== helpers =====================
__device__ __forceinline__ uint32_t smem_u32(const void* p) {
    uint32_t a;
    asm("{ .reg .u64 t; cvta.to.shared.u64 t, %1; cvt.u32.u64 %0, t; }" : "=r"(a) : "l"(p));
    return a;
}
__device__ __forceinline__ void cp16(uint32_t dst, const void* src, uint32_t nbytes) {
    asm volatile("cp.async.cg.shared.global [%0], [%1], 16, %2;"
                 :: "r"(dst), "l"(src), "r"(nbytes) : "memory");
}
__device__ __forceinline__ void cp_commit() {
    asm volatile("cp.async.commit_group;" ::: "memory");
}
template <int N>
__device__ __forceinline__ void cp_wait() {
    asm volatile("cp.async.wait_group %0;" :: "n"(N) : "memory");
}
__device__ __forceinline__ void ldsm4(uint32_t* r, uint32_t a) {
    asm volatile("ldmatrix.sync.aligned.m8n8.x4.shared.b16 {%0,%1,%2,%3}, [%4];"
        : "=r"(r[0]), "=r"(r[1]), "=r"(r[2]), "=r"(r[3]) : "r"(a));
}
__device__ __forceinline__ void mma_f16(float* d, const uint32_t* a, const uint32_t* bq) {
    asm volatile("mma.sync.aligned.m16n8k16.row.col.f32.f16.f16.f32 "
        "{%0,%1,%2,%3}, {%4,%5,%6,%7}, {%8,%9}, {%0,%1,%2,%3};"
        : "+f"(d[0]), "+f"(d[1]), "+f"(d[2]), "+f"(d[3])
        : "r"(a[0]), "r"(a[1]), "r"(a[2]), "r"(a[3]), "r"(bq[0]), "r"(bq[1]));
}
__device__ __forceinline__ uint32_t pack_f16(float hi_el, float lo_el) { // lo16 = lo_el
    uint32_t r;
    asm("cvt.rn.f16x2.f32 %0, %1, %2;" : "=r"(r) : "f"(hi_el), "f"(lo_el));
    return r;
}

// ===================== 0) weight prep: fp16 hi/lo split + im2col chunk reorder =====================
__global__ void k_prep_w(const float* __restrict__ prew, const float* __restrict__ c0w,
                         const float* __restrict__ c1w) {
    for (int idx = blockIdx.x * blockDim.x + threadIdx.x; idx < WTOT; idx += gridDim.x * blockDim.x) {
        int chunk = idx / 12288, rem = idx % 12288;
        int oc = rem >> 6, i = rem & 63;
        float v;
        if (chunk < 3) {
            v = prew[oc * CIN + chunk * 64 + i];
        } else if (chunk < 12) {
            int cc = chunk - 3, tau = cc / 3, ic = (cc % 3) * 64 + i;
            v = c0w[(oc * H + ic) * 3 + tau];
        } else {
            int cc = chunk - 12, tau = cc / 3, ic = (cc % 3) * 64 + i;
            v = c1w[(oc * H + ic) * 3 + tau];
        }
        __half hb = __float2half_rn(v);
        g_w_h[idx] = hb;
        g_w_l[idx] = __float2half_rn(v - __half2float(hb));
    }
}

// ===================== 1) per-batch inclusive scan (warp-shfl) =====================
__global__ void k_cumsum(const int* __restrict__ w) {
    __shared__ int wsum[8];
    int b = blockIdx.x, tid = threadIdx.x;   // 256 threads, 4 elems/thread
    int lane = tid & 31, wr = tid >> 5;
    int base = b * NPH + tid * 4;
    int v0 = w[base], v1 = w[base + 1], v2 = w[base + 2], v3 = w[base + 3];
    int s = v0 + v1 + v2 + v3;
    int ss = s;
#pragma unroll
    for (int off = 1; off < 32; off <<= 1) {
        int t = __shfl_up_sync(0xffffffffu, ss, off);
        if (lane >= off) ss += t;
    }
    if (lane == 31) wsum[wr] = ss;
    __syncthreads();
    int wofs = 0;
#pragma unroll
    for (int i = 0; i < 8; i++) wofs += (i < wr) ? wsum[i] : 0;
    int run = wofs + ss - s;
    run += v0; g_ends[base] = run;
    run += v1; g_ends[base + 1] = run;
    run += v2; g_ends[base + 2] = run;
    run += v3; g_ends[base + 3] = run;
}

// ===================== 2) segment mean -> fp16 plane [b][j][c] (division-free) =====================
#define SEG_J 8
__global__ void k_segmean(const float* __restrict__ x) {
    __shared__ float fr[CIN][SEG_J * 7 + 1];
    __shared__ int se[SEG_J + 1];
    int b = blockIdx.y, j0 = blockIdx.x * SEG_J, tid = threadIdx.x;
    if (tid <= SEG_J) {
        int j = j0 + tid - 1;
        se[tid] = (j >= 0) ? g_ends[b * NPH + j] : 0;
    }
    __syncthreads();
    int t0 = se[0], L = se[SEG_J] - t0;
    const float* xb = x + (size_t)b * CIN * T_FRAMES + t0;
    {
        int cg = tid >> 3, tl = tid & 7;
        for (int c = cg; c < CIN; c += 32)
            for (int tt = tl; tt < L; tt += 8)
                fr[c][tt] = xb[c * T_FRAMES + tt];
    }
    __syncthreads();
    for (int idx = tid; idx < CIN * SEG_J; idx += blockDim.x) {
        int c = idx >> 3, jj = idx & 7;
        int s = se[jj] - t0, e = se[jj + 1] - t0;
        float acc = 0.f;
        for (int tt = s; tt < e; ++tt) acc += fr[c][tt];
        float v = (e > s) ? acc / (float)(e - s) : 0.f;
        g_spec_h[(b * NPH + j0 + jj) * H + c] = __float2half_rn(v);
    }
}

// ===================== 3) fused HMMA GEMM layer (fp16, NTERMS split terms) =====================
// MODE 0: pre (K=192): (D+bias)*m -> h0
// MODE 1: conv0 (K=576): relu((D+b)*m)*m -> LN -> *m*m -> a0
// MODE 2: conv1: ... -> LN -> *m -> linear(4) + lb -> *m -> out
template <int NCHUNKS, int NTAPS, int MODE, int NTERMS>
__global__ void __launch_bounds__(NTHR, 1)
k_fused(const float* __restrict__ bias_g, const float* __restrict__ xmask,
        const float* __restrict__ lng, const float* __restrict__ lnb,
        const float* __restrict__ linw, const float* __restrict__ linb,
        int wofs, float* __restrict__ outp) {
    extern __shared__ char smem[];
    const uint32_t sb = smem_u32(smem);
    const int tid  = threadIdx.x;
    const int lane = tid & 31;
    const int wid  = tid >> 5;
    const int wm   = wid >> 2;   // 0..1 (m 64-slice)
    const int wn   = wid & 3;    // 0..3 (n 48-slice)
    const int b    = blockIdx.y;
    const int j0   = blockIdx.x * JT;

    const uint32_t* inH = (const uint32_t*)(MODE == 0 ? g_spec_h : (MODE == 1 ? g_h0_h : g_a0_h));
    uint32_t* outH = (uint32_t*)(MODE == 0 ? g_h0_h : g_a0_h);
    const uint32_t* wH = ((const uint32_t*)g_w_h) + (wofs >> 1);
    const uint32_t* wL = ((const uint32_t*)g_w_l) + (wofs >> 1);

    float* par = (float*)smem;
    for (int i = tid; i < H; i += NTHR) par[i] = bias_g[i];
    if (MODE != 0)
        for (int i = tid; i < H; i += NTHR) { par[192 + i] = lng[i]; par[384 + i] = lnb[i]; }
    if (MODE == 2) {
        for (int i = tid; i < NOUT * H; i += NTHR) par[576 + i] = linw[i];
        if (tid < NOUT) par[1344 + tid] = linb[tid];
    }

    auto stage = [&](int c, int bi) {
        const int tau = (NTAPS == 3) ? c / 3 : 0;
        const int icb = (NTAPS == 3) ? c % 3 : c;
        const uint32_t bufb = sb + SM_BUF0 + bi * BUF_STRIDE;
        // A: 128 rows x 8 x 16B (single fp16 plane)
#pragma unroll
        for (int i = 0; i < 4; i++) {
            int idx = tid + i * NTHR;
            int row = idx >> 3, seg = idx & 7;
            int jr = j0 + row + ((NTAPS == 3) ? tau - 1 : 0);
            uint32_t ok = ((unsigned)jr < NPH) ? 16u : 0u;
            int jrc = (jr < 0) ? 0 : (jr >= NPH ? NPH - 1 : jr);
            int s = (b * NPH + jrc) * 96 + icb * 32 + seg * 4;
            cp16(bufb + OF_AH + (uint32_t)(row * 144 + seg * 16), inH + s, ok);
        }
        // B: 192 rows x 8 x 16B per plane (hi, + lo when NTERMS==2)
#pragma unroll
        for (int i = 0; i < 6; i++) {
            int idx = tid + i * NTHR;
            int row = idx >> 3, seg = idx & 7;
            int s = c * 6144 + idx * 4;
            uint32_t d = (uint32_t)(row * 144 + seg * 16);
            cp16(bufb + OF_BH + d, wH + s, 16u);
            if (NTERMS == 2) cp16(bufb + OF_BL + d, wL + s, 16u);
        }
        cp_commit();
    };

    float acc[4][6][4];
#pragma unroll
    for (int mt = 0; mt < 4; mt++)
#pragma unroll
        for (int nt = 0; nt < 6; nt++)
#pragma unroll
            for (int q = 0; q < 4; q++) acc[mt][nt][q] = 0.f;

    stage(0, 0);

#pragma unroll 1
    for (int c = 0; c < NCHUNKS; c++) {
        __syncthreads();                       // buffer (c+1)&1 free (mma of c-1 done)
        if (c + 1 < NCHUNKS) stage(c + 1, (c + 1) & 1);
        if (c + 1 < NCHUNKS) cp_wait<1>(); else cp_wait<0>();
        __syncthreads();                       // chunk c visible to all warps
        const uint32_t bufb = sb + SM_BUF0 + (c & 1) * BUF_STRIDE;

#pragma unroll 1
        for (int ks = 0; ks < 4; ks++) {
            uint32_t ah[4][4], bh[6][2], bl[6][2];
            {
                int t = lane >> 3, r = lane & 7;
                int rowA = 64 * wm + r + ((t & 1) << 3);
                int colA = (ks << 4) + ((t & 2) << 2);
                uint32_t aoff = (uint32_t)(rowA * 144 + colA * 2);
#pragma unroll
                for (int mt = 0; mt < 4; mt++)
                    ldsm4(ah[mt], bufb + OF_AH + aoff + mt * (16 * 144));
                int g = lane >> 3, rr = lane & 7;
                int rowBb = 48 * wn + ((g >> 1) << 3) + rr;
                int colB = (ks << 4) + ((g & 1) << 3);
                uint32_t boff0 = (uint32_t)(rowBb * 144 + colB * 2);
#pragma unroll
                for (int p = 0; p < 3; p++) {
                    uint32_t tmp[4];
                    ldsm4(tmp, bufb + OF_BH + boff0 + p * (16 * 144));
                    bh[2 * p][0] = tmp[0]; bh[2 * p][1] = tmp[1];
                    bh[2 * p + 1][0] = tmp[2]; bh[2 * p + 1][1] = tmp[3];
                    if (NTERMS == 2) {
                        ldsm4(tmp, bufb + OF_BL + boff0 + p * (16 * 144));
                        bl[2 * p][0] = tmp[0]; bl[2 * p][1] = tmp[1];
                        bl[2 * p + 1][0] = tmp[2]; bl[2 * p + 1][1] = tmp[3];
                    }
                }
            }
#pragma unroll
            for (int mt = 0; mt < 4; mt++)
#pragma unroll
                for (int nt = 0; nt < 6; nt++) {
                    mma_f16(acc[mt][nt], ah[mt], bh[nt]);
                    if (NTERMS == 2) mma_f16(acc[mt][nt], ah[mt], bl[nt]);
                }
        }
    }
    __syncthreads();   // stage smem dead; safe to overlay reductions

    if (MODE == 0) {
#pragma unroll
        for (int mt = 0; mt < 4; mt++)
#pragma unroll
            for (int t = 0; t < 2; t++) {
                int jloc = 64 * wm + 16 * mt + (lane >> 2) + 8 * t;
                int j = j0 + jloc;
                float m = xmask[b * NPH + j];
                uint32_t* oH = outH + (b * NPH + j) * 96;
#pragma unroll
                for (int nt = 0; nt < 6; nt++) {
                    int c0 = 48 * wn + 8 * nt + (lane & 3) * 2;
                    float v0 = (acc[mt][nt][2 * t + 0] + par[c0])     * m;
                    float v1 = (acc[mt][nt][2 * t + 1] + par[c0 + 1]) * m;
                    oH[c0 >> 1] = pack_f16(v1, v0);
                }
            }
        return;
    }

    float* redS1 = (float*)(smem + SM_BUF0);        // [128][4]
    float* redS2 = redS1 + 512;                     // [128][4]
    float* redLin = redS2 + 512;                    // [4][128][4]

#pragma unroll
    for (int mt = 0; mt < 4; mt++)
#pragma unroll
        for (int t = 0; t < 2; t++) {
            int jloc = 64 * wm + 16 * mt + (lane >> 2) + 8 * t;
            float m = xmask[b * NPH + j0 + jloc];
            float s1 = 0.f, s2 = 0.f;
#pragma unroll
            for (int nt = 0; nt < 6; nt++) {
                int c0 = 48 * wn + 8 * nt + (lane & 3) * 2;
#pragma unroll
                for (int q = 0; q < 2; q++) {
                    float v = fmaxf((acc[mt][nt][2 * t + q] + par[c0 + q]) * m, 0.f) * m;
                    s1 += v; s2 += v * v;
                }
            }
            s1 += __shfl_xor_sync(0xffffffffu, s1, 1); s1 += __shfl_xor_sync(0xffffffffu, s1, 2);
            s2 += __shfl_xor_sync(0xffffffffu, s2, 1); s2 += __shfl_xor_sync(0xffffffffu, s2, 2);
            if ((lane & 3) == 0) { redS1[jloc * 4 + wn] = s1; redS2[jloc * 4 + wn] = s2; }
        }
    __syncthreads();

#pragma unroll
    for (int mt = 0; mt < 4; mt++)
#pragma unroll
        for (int t = 0; t < 2; t++) {
            int jloc = 64 * wm + 16 * mt + (lane >> 2) + 8 * t;
            int j = j0 + jloc;
            float m = xmask[b * NPH + j];
            float s1 = redS1[jloc * 4 + 0] + redS1[jloc * 4 + 1] + redS1[jloc * 4 + 2] + redS1[jloc * 4 + 3];
            float s2 = redS2[jloc * 4 + 0] + redS2[jloc * 4 + 1] + redS2[jloc * 4 + 2] + redS2[jloc * 4 + 3];
            float mean = s1 * (1.f / H);
            float rstd = rsqrtf(s2 * (1.f / H) - mean * mean + EPS);
            if (MODE == 1) {
                uint32_t* oH = outH + (b * NPH + j) * 96;
#pragma unroll
                for (int nt = 0; nt < 6; nt++) {
                    int c0 = 48 * wn + 8 * nt + (lane & 3) * 2;
                    float v0 = fmaxf((acc[mt][nt][2 * t + 0] + par[c0])     * m, 0.f) * m;
                    float v1 = fmaxf((acc[mt][nt][2 * t + 1] + par[c0 + 1]) * m, 0.f) * m;
                    float y0 = ((v0 - mean) * rstd * par[192 + c0]     + par[384 + c0])     * m * m;
                    float y1 = ((v1 - mean) * rstd * par[192 + c0 + 1] + par[384 + c0 + 1]) * m * m;
                    oH[c0 >> 1] = pack_f16(y1, y0);
                }
            } else {
                float p0 = 0.f, p1 = 0.f, p2 = 0.f, p3 = 0.f;
#pragma unroll
                for (int nt = 0; nt < 6; nt++) {
                    int c0 = 48 * wn + 8 * nt + (lane & 3) * 2;
#pragma unroll
                    for (int q = 0; q < 2; q++) {
                        int cc = c0 + q;
                        float v = fmaxf((acc[mt][nt][2 * t + q] + par[cc]) * m, 0.f) * m;
                        float y = ((v - mean) * rstd * par[192 + cc] + par[384 + cc]) * m;
                        p0 += y * par[576 + 0 * H + cc];
                        p1 += y * par[576 + 1 * H + cc];
                        p2 += y * par[576 + 2 * H + cc];
                        p3 += y * par[576 + 3 * H + cc];
                    }
                }
                p0 += __shfl_xor_sync(0xffffffffu, p0, 1); p0 += __shfl_xor_sync(0xffffffffu, p0, 2);
                p1 += __shfl_xor_sync(0xffffffffu, p1, 1); p1 += __shfl_xor_sync(0xffffffffu, p1, 2);
                p2 += __shfl_xor_sync(0xffffffffu, p2, 1); p2 += __shfl_xor_sync(0xffffffffu, p2, 2);
                p3 += __shfl_xor_sync(0xffffffffu, p3, 1); p3 += __shfl_xor_sync(0xffffffffu, p3, 2);
                if ((lane & 3) == 0) {
                    redLin[(0 * 128 + jloc) * 4 + wn] = p0;
                    redLin[(1 * 128 + jloc) * 4 + wn] = p1;
                    redLin[(2 * 128 + jloc) * 4 + wn] = p2;
                    redLin[(3 * 128 + jloc) * 4 + wn] = p3;
                }
            }
        }

    if (MODE == 2) {
        __syncthreads();
        for (int oj = tid; oj < 512; oj += NTHR) {
            int o = oj >> 7, jl = oj & 127;
            float s = redLin[(o * 128 + jl) * 4 + 0] + redLin[(o * 128 + jl) * 4 + 1]
                    + redLin[(o * 128 + jl) * 4 + 2] + redLin[(o * 128 + jl) * 4 + 3];
            s += par[1344 + o];
            s *= xmask[b * NPH + j0 + jl];
            outp[(b * NOUT + o) * NPH + j0 + jl] = s;
        }
    }
}

// ===================== launch =====================
extern "C" void kernel_launch(void* const* d_in, const int* in_sizes, int n_in,
                              void* d_out, int out_size) {
    (void)in_sizes; (void)n_in; (void)out_size;
    const float* x    = (const float*)d_in[0];
    const float* xm   = (const float*)d_in[1];
    const int*   w    = (const int*)d_in[2];
    const float* prew = (const float*)d_in[3];
    const float* preb = (const float*)d_in[4];
    const float* c0w  = (const float*)d_in[5];
    const float* c0b  = (const float*)d_in[6];
    const float* g0   = (const float*)d_in[7];
    const float* b0   = (const float*)d_in[8];
    const float* c1w  = (const float*)d_in[9];
    const float* c1b  = (const float*)d_in[10];
    const float* g1   = (const float*)d_in[11];
    const float* b1   = (const float*)d_in[12];
    const float* lw   = (const float*)d_in[13];
    const float* lb   = (const float*)d_in[14];
    float* out = (float*)d_out;

    cudaFuncSetAttribute((const void*)k_fused<3, 1, 0, 2>, cudaFuncAttributeMaxDynamicSharedMemorySize, SMEM_BYTES);
    cudaFuncSetAttribute((const void*)k_fused<9, 3, 1, 2>, cudaFuncAttributeMaxDynamicSharedMemorySize, SMEM_BYTES);
    cudaFuncSetAttribute((const void*)k_fused<9, 3, 2, 1>, cudaFuncAttributeMaxDynamicSharedMemorySize, SMEM_BYTES);

    k_prep_w<<<252, 256>>>(prew, c0w, c1w);
    k_cumsum<<<BATCH, 256>>>(w);
    k_segmean<<<dim3(NPH / SEG_J, BATCH), 256>>>(x);

    dim3 cg(NPH / JT, BATCH);
    k_fused<3, 1, 0, 2><<<cg, NTHR, SMEM_BYTES>>>(preb, xm, nullptr, nullptr, nullptr, nullptr, 0, nullptr);
    k_fused<9, 3, 1, 2><<<cg, NTHR, SMEM_BYTES>>>(c0b, xm, g0, b0, nullptr, nullptr, 3 * 12288, nullptr);
    k_fused<9, 3, 2, 1><<<cg, NTHR, SMEM_BYTES>>>(c1b, xm, g1, b1, lw, lb, 12 * 12288, out);
}